// round 4
// baseline (speedup 1.0000x reference)
#include <cuda_runtime.h>
#include <cstdint>

#define NN 100000      // input nodes
#define MM 100000      // output nodes
#define NNZ_C 3200000  // edges
#define BB 32          // batch

// Scratch
__device__ float g_xt[NN * BB];      // x transposed (N, 32), 12.8 MB
__device__ int   g_cnt[MM];          // per-dst degree
__device__ int   g_base[MM];         // segment base per dst
__device__ int   g_fill[MM];         // fill cursor per dst
__device__ int2  g_pair[NNZ_C];      // (src, val_bits) grouped by dst, 25.6 MB
__device__ int   g_gcur;             // global segment cursor

// ---------------------------------------------------------------------------
// 1) zero counters + cursor
// ---------------------------------------------------------------------------
__global__ void zero_cnt_kernel() {
    int i = blockIdx.x * blockDim.x + threadIdx.x;
    if (i < MM) g_cnt[i] = 0;
    if (i == 0) g_gcur = 0;
}

// ---------------------------------------------------------------------------
// 2) transpose x (B, N) -> x_t (N, B).  256 threads, 128-n x 32-b tile, f4 I/O
// ---------------------------------------------------------------------------
__global__ void transpose_in_kernel(const float* __restrict__ x) {
    __shared__ float tile[128][33];
    int n0 = blockIdx.x * 128;
    int t = threadIdx.x;
#pragma unroll
    for (int i = 0; i < 4; i++) {
        int idx = i * 256 + t;      // 0..1023
        int b = idx >> 5;           // 0..31
        int q = idx & 31;           // float4 index along n
        int n = n0 + q * 4;
        if (n + 3 < NN) {
            float4 xv = __ldg((const float4*)(x + b * NN + n));
            tile[q * 4 + 0][b] = xv.x;
            tile[q * 4 + 1][b] = xv.y;
            tile[q * 4 + 2][b] = xv.z;
            tile[q * 4 + 3][b] = xv.w;
        } else {
#pragma unroll
            for (int j = 0; j < 4; j++)
                if (n + j < NN) tile[q * 4 + j][b] = x[b * NN + n + j];
        }
    }
    __syncthreads();
#pragma unroll
    for (int i = 0; i < 4; i++) {
        int idx = i * 256 + t;
        int nloc = idx >> 3;        // 0..127
        int b4 = idx & 7;
        int n = n0 + nloc;
        if (n < NN) {
            float4 o;
            o.x = tile[nloc][b4 * 4 + 0];
            o.y = tile[nloc][b4 * 4 + 1];
            o.z = tile[nloc][b4 * 4 + 2];
            o.w = tile[nloc][b4 * 4 + 3];
            *(float4*)(g_xt + n * BB + b4 * 4) = o;
        }
    }
}

// ---------------------------------------------------------------------------
// 3) histogram of dst (4 edges per thread)
// ---------------------------------------------------------------------------
__global__ void hist_kernel(const int* __restrict__ dst) {
    int i = blockIdx.x * blockDim.x + threadIdx.x;   // 0..NNZ/4-1
    int4 d = __ldg((const int4*)dst + i);
    atomicAdd(&g_cnt[d.x], 1);
    atomicAdd(&g_cnt[d.y], 1);
    atomicAdd(&g_cnt[d.z], 1);
    atomicAdd(&g_cnt[d.w], 1);
}

// ---------------------------------------------------------------------------
// 4) segment bases: block exclusive scan + one global atomic per block.
//    (segment ORDER across dsts is arbitrary; only contiguity matters)
// ---------------------------------------------------------------------------
__global__ void assign_base_kernel() {
    __shared__ int sh[1024];
    __shared__ int blockbase;
    int tid = threadIdx.x;
    int idx = blockIdx.x * 1024 + tid;
    int c = (idx < MM) ? g_cnt[idx] : 0;
    sh[tid] = c;
    __syncthreads();
#pragma unroll
    for (int off = 1; off < 1024; off <<= 1) {
        int add = (tid >= off) ? sh[tid - off] : 0;
        __syncthreads();
        sh[tid] += add;
        __syncthreads();
    }
    if (tid == 1023) blockbase = atomicAdd(&g_gcur, sh[1023]);
    __syncthreads();
    int base = blockbase + sh[tid] - c;   // exclusive within block + block base
    if (idx < MM) {
        g_base[idx] = base;
        g_fill[idx] = base;
    }
}

// ---------------------------------------------------------------------------
// 5) permute edges into dst-grouped (src, val) pairs (4 edges per thread)
// ---------------------------------------------------------------------------
__global__ void permute_kernel(const int* __restrict__ src,
                               const int* __restrict__ dst,
                               const float* __restrict__ vals) {
    int i = blockIdx.x * blockDim.x + threadIdx.x;
    int4   s = __ldg((const int4*)src + i);
    int4   d = __ldg((const int4*)dst + i);
    float4 v = __ldg((const float4*)vals + i);
    int p;
    p = atomicAdd(&g_fill[d.x], 1); g_pair[p] = make_int2(s.x, __float_as_int(v.x));
    p = atomicAdd(&g_fill[d.y], 1); g_pair[p] = make_int2(s.y, __float_as_int(v.y));
    p = atomicAdd(&g_fill[d.z], 1); g_pair[p] = make_int2(s.z, __float_as_int(v.z));
    p = atomicAdd(&g_fill[d.w], 1); g_pair[p] = make_int2(s.w, __float_as_int(v.w));
}

// ---------------------------------------------------------------------------
// 6) gather: one warp per dst, 32 dsts per block. Register accumulation,
//    warp reduce, fused transpose + bias writeout (no atomics anywhere).
// ---------------------------------------------------------------------------
__global__ void gather_kernel(float* __restrict__ out,
                              const float* __restrict__ bias) {
    __shared__ float tile[32][33];
    int w = threadIdx.x >> 5;
    int lane = threadIdx.x & 31;
    int m = blockIdx.x * 32 + w;
    int seg = lane & 7;    // float4 slice of the 32-wide batch row
    int sub = lane >> 3;   // 4 concurrent edges

    float4 acc = make_float4(0.f, 0.f, 0.f, 0.f);
    if (m < MM) {
        int base = g_base[m];
        int cnt = g_cnt[m];
        const float4* xt4 = (const float4*)g_xt;
        for (int k = sub; k < cnt; k += 4) {
            int2 pr = __ldg(&g_pair[base + k]);   // 8 lanes broadcast
            float v = __int_as_float(pr.y);
            float4 xv = __ldg(&xt4[pr.x * 8 + seg]);
            acc.x += xv.x * v;
            acc.y += xv.y * v;
            acc.z += xv.z * v;
            acc.w += xv.w * v;
        }
    }
    // reduce partial sums across the 4 sub-groups (lanes xor 8, 16)
#pragma unroll
    for (int off = 8; off <= 16; off <<= 1) {
        acc.x += __shfl_xor_sync(0xffffffffu, acc.x, off);
        acc.y += __shfl_xor_sync(0xffffffffu, acc.y, off);
        acc.z += __shfl_xor_sync(0xffffffffu, acc.z, off);
        acc.w += __shfl_xor_sync(0xffffffffu, acc.w, off);
    }
    if (sub == 0) {
        tile[w][seg * 4 + 0] = acc.x;
        tile[w][seg * 4 + 1] = acc.y;
        tile[w][seg * 4 + 2] = acc.z;
        tile[w][seg * 4 + 3] = acc.w;
    }
    __syncthreads();
    // writeout: warp = batch b, lane = local m  -> coalesced 128B rows
    int b = w;
    int mg = blockIdx.x * 32 + lane;
    if (mg < MM)
        out[b * MM + mg] = tile[lane][b] + __ldg(&bias[mg]);
}

// ---------------------------------------------------------------------------
extern "C" void kernel_launch(void* const* d_in, const int* in_sizes, int n_in,
                              void* d_out, int out_size) {
    const float* x       = (const float*)d_in[0];   // (B, N, 1)
    const int*   indices = (const int*)d_in[1];     // (2, NNZ)
    const float* vals    = (const float*)d_in[2];   // (NNZ,)
    const float* bias    = (const float*)d_in[3];   // (M, 1)
    float* out = (float*)d_out;                     // (B, M, 1)

    const int* src = indices;
    const int* dst = indices + NNZ_C;

    zero_cnt_kernel<<<(MM + 1023) / 1024, 1024>>>();
    transpose_in_kernel<<<(NN + 127) / 128, 256>>>(x);
    hist_kernel<<<NNZ_C / 4 / 256, 256>>>(dst);
    assign_base_kernel<<<(MM + 1023) / 1024, 1024>>>();
    permute_kernel<<<NNZ_C / 4 / 256, 256>>>(src, dst, vals);
    gather_kernel<<<(MM + 31) / 32, 1024>>>(out, bias);
}

// round 7
// speedup vs baseline: 1.9713x; 1.9713x over previous
#include <cuda_runtime.h>
#include <cstdint>

#define NN 100000      // input nodes
#define MM 100000      // output nodes
#define NNZ_C 3200000  // edges (divisible by 32)
#define BB 32          // batch

// Scratch: batch-contiguous transposed copies (12.8 MB each)
__device__ float g_xt[NN * BB];   // x_t[n][b]
__device__ float g_yt[MM * BB];   // y_t[m][b] accumulator

// ---------------------------------------------------------------------------
// Kernel 1: zero the accumulator (float4 grid-stride, wide grid)
// ---------------------------------------------------------------------------
__global__ void zero_yt_kernel() {
    float4* p = reinterpret_cast<float4*>(g_yt);
    const int total = (MM * BB) / 4;   // 800000
    for (int i = blockIdx.x * blockDim.x + threadIdx.x; i < total;
         i += gridDim.x * blockDim.x) {
        p[i] = make_float4(0.f, 0.f, 0.f, 0.f);
    }
}

// ---------------------------------------------------------------------------
// Kernel 2: transpose x (B, N) -> x_t (N, B). 256 threads, 128x32 tile, f4 I/O
// ---------------------------------------------------------------------------
__global__ void transpose_in_kernel(const float* __restrict__ x) {
    __shared__ float tile[128][33];
    int n0 = blockIdx.x * 128;
    int t = threadIdx.x;
#pragma unroll
    for (int i = 0; i < 4; i++) {
        int idx = i * 256 + t;      // 0..1023
        int b = idx >> 5;           // batch row 0..31
        int q = idx & 31;           // float4 index along n
        int n = n0 + q * 4;
        if (n + 3 < NN) {
            float4 xv = __ldg((const float4*)(x + b * NN + n));
            tile[q * 4 + 0][b] = xv.x;
            tile[q * 4 + 1][b] = xv.y;
            tile[q * 4 + 2][b] = xv.z;
            tile[q * 4 + 3][b] = xv.w;
        } else {
#pragma unroll
            for (int j = 0; j < 4; j++)
                if (n + j < NN) tile[q * 4 + j][b] = x[b * NN + n + j];
        }
    }
    __syncthreads();
#pragma unroll
    for (int i = 0; i < 4; i++) {
        int idx = i * 256 + t;
        int nloc = idx >> 3;        // 0..127
        int b4 = idx & 7;
        int n = n0 + nloc;
        if (n < NN) {
            float4 o;
            o.x = tile[nloc][b4 * 4 + 0];
            o.y = tile[nloc][b4 * 4 + 1];
            o.z = tile[nloc][b4 * 4 + 2];
            o.w = tile[nloc][b4 * 4 + 3];
            *(float4*)(g_xt + n * BB + b4 * 4) = o;
        }
    }
}

// ---------------------------------------------------------------------------
// Kernel 3: edge scatter. Each warp owns 32 edges (coalesced edge loads),
// processes 4 edges at a time: 8 lanes per edge, float4 per lane.
// gather: 128B line from x_t[src];  scatter: red.global.add.v4.f32 -> y_t[dst]
// NNZ divisible by 32 -> no bounds checks.
// ---------------------------------------------------------------------------
__global__ void __launch_bounds__(256) edge_kernel(
        const int* __restrict__ src,
        const int* __restrict__ dst,
        const float* __restrict__ vals) {
    int gtid = blockIdx.x * blockDim.x + threadIdx.x;
    int warp_id = gtid >> 5;
    int lane = threadIdx.x & 31;

    int e = warp_id * 32 + lane;
    int   s = __ldg(&src[e]);
    int   d = __ldg(&dst[e]);
    float v = __ldg(&vals[e]);

    int seg = lane & 7;   // which float4 of the 32-float row
    int sub = lane >> 3;  // which of 4 concurrent edges

    const float4* xt4 = reinterpret_cast<const float4*>(g_xt);

#pragma unroll
    for (int j = 0; j < 8; j++) {
        int eidx = j * 4 + sub;
        int   se = __shfl_sync(0xffffffffu, s, eidx);
        int   de = __shfl_sync(0xffffffffu, d, eidx);
        float ve = __shfl_sync(0xffffffffu, v, eidx);
        float4 xv = __ldg(&xt4[se * 8 + seg]);
        float cx = xv.x * ve, cy = xv.y * ve, cz = xv.z * ve, cw = xv.w * ve;
        float* p = g_yt + de * BB + seg * 4;
        asm volatile(
            "red.global.add.v4.f32 [%0], {%1, %2, %3, %4};"
            :: "l"(p), "f"(cx), "f"(cy), "f"(cz), "f"(cw)
            : "memory");
    }
}

// ---------------------------------------------------------------------------
// Kernel 4: out (B, M) = transpose(y_t (M, B)) + bias.
// 256 threads, 128-m x 32-b tile, float4 both directions.
// ---------------------------------------------------------------------------
__global__ void transpose_out_kernel(float* __restrict__ out,
                                     const float* __restrict__ bias) {
    __shared__ float tile[32][129];   // [b][m_local]  (+1 col padding)
    int m0 = blockIdx.x * 128;
    int t = threadIdx.x;
    // read: y_t rows (m, :) as float4 along b.  8 threads cover one m-row.
#pragma unroll
    for (int i = 0; i < 4; i++) {
        int idx = i * 256 + t;      // 0..1023
        int mloc = idx >> 3;        // 0..127
        int b4 = idx & 7;
        int m = m0 + mloc;
        if (m < MM) {
            float4 yv = *(const float4*)(g_yt + m * BB + b4 * 4);
            float bi = __ldg(&bias[m]);
            tile[b4 * 4 + 0][mloc] = yv.x + bi;
            tile[b4 * 4 + 1][mloc] = yv.y + bi;
            tile[b4 * 4 + 2][mloc] = yv.z + bi;
            tile[b4 * 4 + 3][mloc] = yv.w + bi;
        }
    }
    __syncthreads();
    // write: out[b][m0 + q*4 .. +3] as float4 along m. 32 threads per b-row.
#pragma unroll
    for (int i = 0; i < 4; i++) {
        int idx = i * 256 + t;
        int b = idx >> 5;           // 0..31
        int q = idx & 31;           // float4 index along m (0..31)
        int m = m0 + q * 4;
        if (m + 3 < MM) {
            float4 o;
            o.x = tile[b][q * 4 + 0];
            o.y = tile[b][q * 4 + 1];
            o.z = tile[b][q * 4 + 2];
            o.w = tile[b][q * 4 + 3];
            *(float4*)(out + b * MM + m) = o;
        } else {
#pragma unroll
            for (int j = 0; j < 4; j++)
                if (m + j < MM) out[b * MM + m + j] = tile[b][q * 4 + j];
        }
    }
}

// ---------------------------------------------------------------------------
extern "C" void kernel_launch(void* const* d_in, const int* in_sizes, int n_in,
                              void* d_out, int out_size) {
    const float* x       = (const float*)d_in[0];   // (B, N, 1)
    const int*   indices = (const int*)d_in[1];     // (2, NNZ)
    const float* vals    = (const float*)d_in[2];   // (NNZ,)
    const float* bias    = (const float*)d_in[3];   // (M, 1)
    float* out = (float*)d_out;                     // (B, M, 1)

    const int* src = indices;
    const int* dst = indices + NNZ_C;

    zero_yt_kernel<<<1600, 256>>>();
    transpose_in_kernel<<<(NN + 127) / 128, 256>>>(x);
    edge_kernel<<<(NNZ_C / 32) * 32 / 256, 256>>>(src, dst, vals);
    transpose_out_kernel<<<(MM + 127) / 128, 256>>>(out, bias);
}